// round 3
// baseline (speedup 1.0000x reference)
#include <cuda_runtime.h>
#include <stdint.h>

// SmoothLDDTLoss — b=2, n=4096.
// Pairs restricted to i<j (symmetric eps/mask => ratio invariant).
// 4 MUFU/pair: 2x sqrt.approx, 1x ex2, 1x rcp (common-denominator sigmoid sum).

#define TILE 128

__device__ double             g_sum[2];
__device__ unsigned long long g_cnt[2];

__device__ __forceinline__ float fsqrt_ap(float x) { float r; asm("sqrt.approx.f32 %0, %1;" : "=f"(r) : "f"(x)); return r; }
__device__ __forceinline__ float frcp_ap (float x) { float r; asm("rcp.approx.f32 %0, %1;"  : "=f"(r) : "f"(x)); return r; }
__device__ __forceinline__ float fex2_ap (float x) { float r; asm("ex2.approx.f32 %0, %1;"  : "=f"(r) : "f"(x)); return r; }

__global__ void init_kernel() {
    if (threadIdx.x < 2) { g_sum[threadIdx.x] = 0.0; g_cnt[threadIdx.x] = 0ull; }
}

__global__ void __launch_bounds__(TILE) lddt_pair_kernel(
    const float* __restrict__ pred,
    const float* __restrict__ truec,
    const uint8_t* __restrict__ is_dna,
    const uint8_t* __restrict__ is_rna,
    const uint8_t* __restrict__ cmask,
    int n, int ntiles)
{
    // Closed-form triangular decode: blockIdx.x = t -> (ti, tj), ti <= tj.
    // Row ti starts at offset ti*ntiles - ti*(ti-1)/2. O(1), no data-dependent loop.
    int t = blockIdx.x;
    float Nf = (float)ntiles;
    float tf = (float)t;
    // solve ti from t ≈ ti*N - ti(ti-1)/2; invert quadratic, then clamp-correct.
    float disc = fmaf(2.0f, Nf, 1.0f);                 // 2N+1
    float s    = sqrtf(fmaf(disc, disc, -8.0f * tf));  // sqrt((2N+1)^2 - 8t)
    int ti = (int)floorf(0.5f * (disc - s));
    if (ti < 0) ti = 0;
    if (ti > ntiles - 1) ti = ntiles - 1;
    // exact correction (at most one step due to fp rounding)
    #pragma unroll
    for (int k = 0; k < 2; k++) {
        int row_off  = ti * ntiles - (ti * (ti - 1)) / 2;
        int next_off = (ti + 1) * ntiles - ((ti + 1) * ti) / 2;
        if (t < row_off)       ti--;
        else if (t >= next_off) ti++;
    }
    int row_off = ti * ntiles - (ti * (ti - 1)) / 2;
    int tj = ti + (t - row_off);
    if (tj < ti) tj = ti;
    if (tj > ntiles - 1) tj = ntiles - 1;

    int b = blockIdx.y;

    __shared__ float s_px[TILE], s_py[TILE], s_pz[TILE];
    __shared__ float s_tx[TILE], s_ty[TILE], s_tz[TILE];
    __shared__ int   s_fl[TILE];   // bit0 = nucleotide, bit1 = coords_mask

    const int tid = threadIdx.x;
    const long base = (long)b * n;

    // ---- load j tile into smem ----
    {
        int jg = tj * TILE + tid;
        float px = 0.f, py = 0.f, pz = 0.f, tx = 0.f, ty = 0.f, tz = 0.f;
        int fl = 0;
        if (jg < n) {
            long idx = (base + jg) * 3;
            px = pred[idx + 0]; py = pred[idx + 1]; pz = pred[idx + 2];
            tx = truec[idx + 0]; ty = truec[idx + 1]; tz = truec[idx + 2];
            int nuc = (__ldg(&is_dna[base + jg]) | __ldg(&is_rna[base + jg])) ? 1 : 0;
            int cm  = __ldg(&cmask[base + jg]) ? 2 : 0;
            fl = nuc | cm;
        }
        s_px[tid] = px; s_py[tid] = py; s_pz[tid] = pz;
        s_tx[tid] = tx; s_ty[tid] = ty; s_tz[tid] = tz;
        s_fl[tid] = fl;
    }
    __syncthreads();

    // ---- own i point in registers ----
    const int ig = ti * TILE + tid;
    float ipx = 0.f, ipy = 0.f, ipz = 0.f, itx = 0.f, ity = 0.f, itz = 0.f;
    int ifl = 0;
    if (ig < n) {
        long idx = (base + ig) * 3;
        ipx = pred[idx + 0]; ipy = pred[idx + 1]; ipz = pred[idx + 2];
        itx = truec[idx + 0]; ity = truec[idx + 1]; itz = truec[idx + 2];
        int nuc = (__ldg(&is_dna[base + ig]) | __ldg(&is_rna[base + ig])) ? 1 : 0;
        int cm  = __ldg(&cmask[base + ig]) ? 2 : 0;
        ifl = nuc | cm;
    }

    // sigmoid constants: e^{-0.5}, e^{-1}, e^{-2}, e^{-4}
    const float C1 = 0.60653065971263342f;
    const float C2 = 0.36787944117144233f;
    const float C3 = 0.13533528323661270f;
    const float C4 = 0.01831563888873418f;
    const float LOG2E = 1.44269504088896340f;

    float acc_sum = 0.f;
    int   acc_cnt = 0;

    const int jbase = tj * TILE;
    #pragma unroll 8
    for (int j = 0; j < TILE; j++) {
        float dx = ipx - s_px[j], dy = ipy - s_py[j], dz = ipz - s_pz[j];
        float dp2 = fmaf(dx, dx, fmaf(dy, dy, dz * dz));
        float ex = itx - s_tx[j], ey = ity - s_ty[j], ez = itz - s_tz[j];
        float dt2 = fmaf(ex, ex, fmaf(ey, ey, ez * ez));

        float dtrue = fsqrt_ap(dt2);
        float dpred = fsqrt_ap(dp2);
        float diff  = fminf(fabsf(dtrue - dpred), 20.0f);

        float e  = fex2_ap(diff * LOG2E);
        float u1 = fmaf(e, C1, 1.0f);
        float u2 = fmaf(e, C2, 1.0f);
        float u3 = fmaf(e, C3, 1.0f);
        float u4 = fmaf(e, C4, 1.0f);
        float A = u1 * u2, B = u3 * u4;
        float num = (u1 + u2) * B + (u3 + u4) * A;
        float eps = num * frcp_ap(A * B);   // = sum of 4 sigmoids

        int fl = s_fl[j];
        int nucpair = ifl & fl & 1;
        float R2 = nucpair ? 900.0f : 225.0f;   // 30^2 : 15^2
        int jg = jbase + j;
        bool valid = (dt2 < R2) & ((ifl & fl & 2) != 0) & (jg > ig) & (jg < n);

        acc_sum += valid ? eps : 0.f;
        acc_cnt += valid ? 1 : 0;
    }

    // ---- block reduce ----
    #pragma unroll
    for (int o = 16; o > 0; o >>= 1) {
        acc_sum += __shfl_down_sync(0xFFFFFFFFu, acc_sum, o);
        acc_cnt += __shfl_down_sync(0xFFFFFFFFu, acc_cnt, o);
    }
    __shared__ float ws[TILE / 32];
    __shared__ int   wc[TILE / 32];
    int w = tid >> 5, l = tid & 31;
    if (l == 0) { ws[w] = acc_sum; wc[w] = acc_cnt; }
    __syncthreads();
    if (tid == 0) {
        float S = 0.f; int C = 0;
        #pragma unroll
        for (int k = 0; k < TILE / 32; k++) { S += ws[k]; C += wc[k]; }
        atomicAdd(&g_sum[b], (double)S * 0.25);   // eps = sum_of_sigmoids / 4
        atomicAdd(&g_cnt[b], (unsigned long long)C);
    }
}

__global__ void finalize_kernel(float* out) {
    double c0 = (double)g_cnt[0]; if (c0 < 1.0) c0 = 1.0;
    double c1 = (double)g_cnt[1]; if (c1 < 1.0) c1 = 1.0;
    double l0 = g_sum[0] / c0;
    double l1 = g_sum[1] / c1;
    out[0] = (float)(1.0 - 0.5 * (l0 + l1));
}

extern "C" void kernel_launch(void* const* d_in, const int* in_sizes, int n_in,
                              void* d_out, int out_size)
{
    const float*   pred  = (const float*)d_in[0];
    const float*   truec = (const float*)d_in[1];
    const uint8_t* dna   = (const uint8_t*)d_in[2];
    const uint8_t* rna   = (const uint8_t*)d_in[3];
    const uint8_t* cm    = (const uint8_t*)d_in[4];

    const int B = 2;
    const int n = in_sizes[2] / B;           // is_dna has b*n elements
    const int ntiles = (n + TILE - 1) / TILE;
    const int npairs = ntiles * (ntiles + 1) / 2;

    init_kernel<<<1, 32>>>();
    dim3 grid(npairs, B);
    lddt_pair_kernel<<<grid, TILE>>>(pred, truec, dna, rna, cm, n, ntiles);
    finalize_kernel<<<1, 1>>>((float*)d_out);
}

// round 4
// speedup vs baseline: 1.0895x; 1.0895x over previous
#include <cuda_runtime.h>
#include <stdint.h>

// SmoothLDDTLoss — b=2, n=4096.
// i<j symmetric halving; float4-packed smem; all-FP mask path;
// 3.5 MUFU/pair (2 sqrt + 1 ex2 + 0.5 batched rcp); 2 launches total.

#define TILE 128

__device__ double g_sum[2];
__device__ double g_cnt[2];

__device__ __forceinline__ float fsqrt_ap(float x) { float r; asm("sqrt.approx.f32 %0, %1;" : "=f"(r) : "f"(x)); return r; }
__device__ __forceinline__ float frcp_ap (float x) { float r; asm("rcp.approx.f32 %0, %1;"  : "=f"(r) : "f"(x)); return r; }
__device__ __forceinline__ float fex2_ap (float x) { float r; asm("ex2.approx.f32 %0, %1;"  : "=f"(r) : "f"(x)); return r; }

// sigmoid constants: e^{-0.5}, e^{-1}, e^{-2}, e^{-4}
#define C1 0.60653065971263342f
#define C2 0.36787944117144233f
#define C3 0.13533528323661270f
#define C4 0.01831563888873418f
#define LOG2E 1.44269504088896340f

// Per-pair eps numerator/denominator: eps*den = num, den = (u1u2)(u3u4)
__device__ __forceinline__ void eps_parts(float dt2, float dp2,
                                          float& num, float& den, float& dt2_out)
{
    float dtrue = fsqrt_ap(dt2);
    float dpred = fsqrt_ap(dp2);
    float diff  = fminf(fabsf(dtrue - dpred), 20.0f);
    float e  = fex2_ap(diff * LOG2E);   // e^{diff}
    float u1 = fmaf(e, C1, 1.0f);
    float u2 = fmaf(e, C2, 1.0f);
    float u3 = fmaf(e, C3, 1.0f);
    float u4 = fmaf(e, C4, 1.0f);
    float A = u1 * u2, B = u3 * u4;
    num = (u1 + u2) * B + (u3 + u4) * A;
    den = A * B;
    dt2_out = dt2;
}

template<bool DIAG>
__device__ __forceinline__ void tile_loop(
    const float4* s_p, const float4* s_t,
    float ipx, float ipy, float ipz, float itx, float ity, float itz,
    float a_i, float cm_i, int ig, int jbase,
    float& acc_sum, float& acc_cnt)
{
    #pragma unroll 4
    for (int j = 0; j < TILE; j += 2) {
        float4 P0 = s_p[j],     T0 = s_t[j];
        float4 P1 = s_p[j + 1], T1 = s_t[j + 1];

        float dx0 = ipx - P0.x, dy0 = ipy - P0.y, dz0 = ipz - P0.z;
        float dp20 = fmaf(dx0, dx0, fmaf(dy0, dy0, dz0 * dz0));
        float ex0 = itx - T0.x, ey0 = ity - T0.y, ez0 = itz - T0.z;
        float dt20 = fmaf(ex0, ex0, fmaf(ey0, ey0, ez0 * ez0));

        float dx1 = ipx - P1.x, dy1 = ipy - P1.y, dz1 = ipz - P1.z;
        float dp21 = fmaf(dx1, dx1, fmaf(dy1, dy1, dz1 * dz1));
        float ex1 = itx - T1.x, ey1 = ity - T1.y, ez1 = itz - T1.z;
        float dt21 = fmaf(ex1, ex1, fmaf(ey1, ey1, ez1 * ez1));

        float num0, den0, d20, num1, den1, d21;
        eps_parts(dt20, dp20, num0, den0, d20);
        eps_parts(dt21, dp21, num1, den1, d21);

        // one rcp for two pairs
        float r    = frcp_ap(den0 * den1);
        float eps0 = num0 * (r * den1);    // = 4*eps (sum of sigmoids)
        float eps1 = num1 * (r * den0);

        // all-FP mask: R2 = nucpair ? 900 : 225; weight = cm_i*cm_j
        float R20 = fmaf(a_i * P0.w, 675.0f, 225.0f);
        float R21 = fmaf(a_i * P1.w, 675.0f, 225.0f);
        float w0 = cm_i * T0.w;
        float w1 = cm_i * T1.w;
        float m0 = (d20 < R20) ? w0 : 0.0f;
        float m1 = (d21 < R21) ? w1 : 0.0f;
        if (DIAG) {
            m0 = (jbase + j     > ig) ? m0 : 0.0f;
            m1 = (jbase + j + 1 > ig) ? m1 : 0.0f;
        }
        acc_sum = fmaf(eps0, m0, acc_sum);
        acc_sum = fmaf(eps1, m1, acc_sum);
        acc_cnt += m0 + m1;
    }
}

__global__ void __launch_bounds__(TILE) lddt_pair_kernel(
    const float* __restrict__ pred,
    const float* __restrict__ truec,
    const uint8_t* __restrict__ is_dna,
    const uint8_t* __restrict__ is_rna,
    const uint8_t* __restrict__ cmask,
    int n, int ntiles)
{
    // Closed-form triangular decode: blockIdx.x -> (ti, tj), ti <= tj.
    int t = blockIdx.x;
    float Nf = (float)ntiles;
    float disc = fmaf(2.0f, Nf, 1.0f);
    float s    = sqrtf(fmaf(disc, disc, -8.0f * (float)t));
    int ti = (int)floorf(0.5f * (disc - s));
    if (ti < 0) ti = 0;
    if (ti > ntiles - 1) ti = ntiles - 1;
    #pragma unroll
    for (int k = 0; k < 2; k++) {
        int row_off  = ti * ntiles - (ti * (ti - 1)) / 2;
        int next_off = (ti + 1) * ntiles - ((ti + 1) * ti) / 2;
        if (t < row_off)        ti--;
        else if (t >= next_off) ti++;
    }
    int row_off = ti * ntiles - (ti * (ti - 1)) / 2;
    int tj = ti + (t - row_off);
    if (tj < ti) tj = ti;
    if (tj > ntiles - 1) tj = ntiles - 1;

    const int b = blockIdx.y;
    const int tid = threadIdx.x;
    const long base = (long)b * n;

    __shared__ float4 s_p[TILE];   // pred x,y,z + nuc flag (1/0)
    __shared__ float4 s_t[TILE];   // true x,y,z + cmask flag (1/0)

    // ---- load j tile ----
    {
        int jg = tj * TILE + tid;
        float4 P = make_float4(0.f, 0.f, 0.f, 0.f);
        float4 T = make_float4(0.f, 0.f, 0.f, 0.f);
        if (jg < n) {
            long idx = (base + jg) * 3;
            P.x = pred[idx + 0]; P.y = pred[idx + 1]; P.z = pred[idx + 2];
            T.x = truec[idx + 0]; T.y = truec[idx + 1]; T.z = truec[idx + 2];
            P.w = (__ldg(&is_dna[base + jg]) | __ldg(&is_rna[base + jg])) ? 1.0f : 0.0f;
            T.w = __ldg(&cmask[base + jg]) ? 1.0f : 0.0f;
        }
        s_p[tid] = P;
        s_t[tid] = T;
    }
    __syncthreads();

    // ---- own i point ----
    const int ig = ti * TILE + tid;
    float ipx = 0.f, ipy = 0.f, ipz = 0.f, itx = 0.f, ity = 0.f, itz = 0.f;
    float a_i = 0.f, cm_i = 0.f;
    if (ig < n) {
        long idx = (base + ig) * 3;
        ipx = pred[idx + 0]; ipy = pred[idx + 1]; ipz = pred[idx + 2];
        itx = truec[idx + 0]; ity = truec[idx + 1]; itz = truec[idx + 2];
        a_i  = (__ldg(&is_dna[base + ig]) | __ldg(&is_rna[base + ig])) ? 1.0f : 0.0f;
        cm_i = __ldg(&cmask[base + ig]) ? 1.0f : 0.0f;
    }

    float acc_sum = 0.f, acc_cnt = 0.f;
    const int jbase = tj * TILE;
    if (ti == tj)
        tile_loop<true >(s_p, s_t, ipx, ipy, ipz, itx, ity, itz, a_i, cm_i, ig, jbase, acc_sum, acc_cnt);
    else
        tile_loop<false>(s_p, s_t, ipx, ipy, ipz, itx, ity, itz, a_i, cm_i, ig, jbase, acc_sum, acc_cnt);

    // ---- block reduce ----
    #pragma unroll
    for (int o = 16; o > 0; o >>= 1) {
        acc_sum += __shfl_down_sync(0xFFFFFFFFu, acc_sum, o);
        acc_cnt += __shfl_down_sync(0xFFFFFFFFu, acc_cnt, o);
    }
    __shared__ float ws[TILE / 32];
    __shared__ float wc[TILE / 32];
    int w = tid >> 5, l = tid & 31;
    if (l == 0) { ws[w] = acc_sum; wc[w] = acc_cnt; }
    __syncthreads();
    if (tid == 0) {
        float S = 0.f, C = 0.f;
        #pragma unroll
        for (int k = 0; k < TILE / 32; k++) { S += ws[k]; C += wc[k]; }
        atomicAdd(&g_sum[b], (double)S * 0.25);   // eps = sum_of_sigmoids / 4
        atomicAdd(&g_cnt[b], (double)C);
    }
}

__global__ void finalize_kernel(float* out) {
    double c0 = g_cnt[0]; if (c0 < 1.0) c0 = 1.0;
    double c1 = g_cnt[1]; if (c1 < 1.0) c1 = 1.0;
    double l0 = g_sum[0] / c0;
    double l1 = g_sum[1] / c1;
    out[0] = (float)(1.0 - 0.5 * (l0 + l1));
    // reset accumulators so each launch (and each graph replay) starts from zero
    g_sum[0] = 0.0; g_sum[1] = 0.0;
    g_cnt[0] = 0.0; g_cnt[1] = 0.0;
}

extern "C" void kernel_launch(void* const* d_in, const int* in_sizes, int n_in,
                              void* d_out, int out_size)
{
    const float*   pred  = (const float*)d_in[0];
    const float*   truec = (const float*)d_in[1];
    const uint8_t* dna   = (const uint8_t*)d_in[2];
    const uint8_t* rna   = (const uint8_t*)d_in[3];
    const uint8_t* cm    = (const uint8_t*)d_in[4];

    const int B = 2;
    const int n = in_sizes[2] / B;           // is_dna has b*n elements
    const int ntiles = (n + TILE - 1) / TILE;
    const int npairs = ntiles * (ntiles + 1) / 2;

    dim3 grid(npairs, B);
    lddt_pair_kernel<<<grid, TILE>>>(pred, truec, dna, rna, cm, n, ntiles);
    finalize_kernel<<<1, 1>>>((float*)d_out);
}

// round 5
// speedup vs baseline: 1.0944x; 1.0045x over previous
#include <cuda_runtime.h>
#include <stdint.h>

// SmoothLDDTLoss — b=2, n=4096. Single fused kernel (last-block finalize).
// i<j symmetric halving; float4 smem; poison-coordinate masking;
// 3.5 MUFU/pair (2 sqrt + 1 ex2 + 0.5 batched rcp).

#define TILE 128

__device__ double       g_sum[2];
__device__ double       g_cnt[2];
__device__ unsigned int g_done;   // zero-initialized at module load; reset by last block

__device__ __forceinline__ float fsqrt_ap(float x) { float r; asm("sqrt.approx.f32 %0, %1;" : "=f"(r) : "f"(x)); return r; }
__device__ __forceinline__ float frcp_ap (float x) { float r; asm("rcp.approx.f32 %0, %1;"  : "=f"(r) : "f"(x)); return r; }
__device__ __forceinline__ float fex2_ap (float x) { float r; asm("ex2.approx.f32 %0, %1;"  : "=f"(r) : "f"(x)); return r; }

// sigmoid constants: e^{-0.5}, e^{-1}, e^{-2}, e^{-4}
#define C1 0.60653065971263342f
#define C2 0.36787944117144233f
#define C3 0.13533528323661270f
#define C4 0.01831563888873418f
#define LOG2E 1.44269504088896340f

__device__ __forceinline__ void eps_parts(float dt2, float dp2, float& num, float& den)
{
    float dtrue = fsqrt_ap(dt2);
    float dpred = fsqrt_ap(dp2);
    float diff  = fminf(fabsf(dtrue - dpred), 20.0f);
    float e  = fex2_ap(diff * LOG2E);   // e^{diff}
    float u1 = fmaf(e, C1, 1.0f);
    float u2 = fmaf(e, C2, 1.0f);
    float u3 = fmaf(e, C3, 1.0f);
    float u4 = fmaf(e, C4, 1.0f);
    float A = u1 * u2, B = u3 * u4;
    num = (u1 + u2) * B + (u3 + u4) * A;
    den = A * B;
}

template<bool DIAG>
__device__ __forceinline__ void tile_loop(
    const float4* s_p, const float4* s_t,
    float ipx, float ipy, float ipz, float itx, float ity, float itz,
    float a_i, int ig, int jbase,
    float& acc_sum, float& acc_cnt)
{
    #pragma unroll 4
    for (int j = 0; j < TILE; j += 2) {
        float4 P0 = s_p[j],     T0 = s_t[j];
        float4 P1 = s_p[j + 1], T1 = s_t[j + 1];

        float dx0 = ipx - P0.x, dy0 = ipy - P0.y, dz0 = ipz - P0.z;
        float dp20 = fmaf(dx0, dx0, fmaf(dy0, dy0, dz0 * dz0));
        float ex0 = itx - T0.x, ey0 = ity - T0.y, ez0 = itz - T0.z;
        float dt20 = fmaf(ex0, ex0, fmaf(ey0, ey0, ez0 * ez0));

        float dx1 = ipx - P1.x, dy1 = ipy - P1.y, dz1 = ipz - P1.z;
        float dp21 = fmaf(dx1, dx1, fmaf(dy1, dy1, dz1 * dz1));
        float ex1 = itx - T1.x, ey1 = ity - T1.y, ez1 = itz - T1.z;
        float dt21 = fmaf(ex1, ex1, fmaf(ey1, ey1, ez1 * ez1));

        float num0, den0, num1, den1;
        eps_parts(dt20, dp20, num0, den0);
        eps_parts(dt21, dp21, num1, den1);

        // one rcp for two pairs
        float r    = frcp_ap(den0 * den1);
        float eps0 = num0 * (r * den1);    // = sum of 4 sigmoids
        float eps1 = num1 * (r * den0);

        // masking: coords_mask already folded in via poisoned true coords.
        // R2 = nucpair ? 900 : 225
        float R20 = fmaf(a_i * P0.w, 675.0f, 225.0f);
        float R21 = fmaf(a_i * P1.w, 675.0f, 225.0f);
        bool v0 = dt20 < R20;
        bool v1 = dt21 < R21;
        if (DIAG) {
            v0 = v0 && (jbase + j     > ig);
            v1 = v1 && (jbase + j + 1 > ig);
        }
        acc_sum += v0 ? eps0 : 0.0f;
        acc_sum += v1 ? eps1 : 0.0f;
        acc_cnt += v0 ? 1.0f : 0.0f;
        acc_cnt += v1 ? 1.0f : 0.0f;
    }
}

__global__ void __launch_bounds__(TILE) lddt_fused_kernel(
    const float* __restrict__ pred,
    const float* __restrict__ truec,
    const uint8_t* __restrict__ is_dna,
    const uint8_t* __restrict__ is_rna,
    const uint8_t* __restrict__ cmask,
    float* __restrict__ out,
    int n, int ntiles, unsigned int total_blocks)
{
    // Closed-form triangular decode: blockIdx.x -> (ti, tj), ti <= tj.
    int t = blockIdx.x;
    float Nf = (float)ntiles;
    float disc = fmaf(2.0f, Nf, 1.0f);
    float s    = sqrtf(fmaf(disc, disc, -8.0f * (float)t));
    int ti = (int)floorf(0.5f * (disc - s));
    if (ti < 0) ti = 0;
    if (ti > ntiles - 1) ti = ntiles - 1;
    #pragma unroll
    for (int k = 0; k < 2; k++) {
        int row_off  = ti * ntiles - (ti * (ti - 1)) / 2;
        int next_off = (ti + 1) * ntiles - ((ti + 1) * ti) / 2;
        if (t < row_off)        ti--;
        else if (t >= next_off) ti++;
    }
    int row_off = ti * ntiles - (ti * (ti - 1)) / 2;
    int tj = ti + (t - row_off);
    if (tj < ti) tj = ti;
    if (tj > ntiles - 1) tj = ntiles - 1;

    const int b = blockIdx.y;
    const int tid = threadIdx.x;
    const long base = (long)b * n;

    __shared__ float4 s_p[TILE];   // pred x,y,z + nuc flag
    __shared__ float4 s_t[TILE];   // true x,y,z (poisoned if masked-out), w unused

    // ---- load j tile ----
    {
        int jg = tj * TILE + tid;
        float4 P = make_float4(0.f, 0.f, 0.f, 0.f);
        float4 T = make_float4(-1e8f, -1e8f, -1e8f, 0.f);   // default: poisoned (out of bounds)
        if (jg < n) {
            long idx = (base + jg) * 3;
            P.x = pred[idx + 0]; P.y = pred[idx + 1]; P.z = pred[idx + 2];
            P.w = (__ldg(&is_dna[base + jg]) | __ldg(&is_rna[base + jg])) ? 1.0f : 0.0f;
            if (__ldg(&cmask[base + jg])) {
                T.x = truec[idx + 0]; T.y = truec[idx + 1]; T.z = truec[idx + 2];
            }
        }
        s_p[tid] = P;
        s_t[tid] = T;
    }
    __syncthreads();

    // ---- own i point ----
    const int ig = ti * TILE + tid;
    float ipx = 0.f, ipy = 0.f, ipz = 0.f;
    float itx = 1e8f, ity = 1e8f, itz = 1e8f;   // opposite-sign poison vs j-side
    float a_i = 0.f;
    if (ig < n) {
        long idx = (base + ig) * 3;
        ipx = pred[idx + 0]; ipy = pred[idx + 1]; ipz = pred[idx + 2];
        a_i = (__ldg(&is_dna[base + ig]) | __ldg(&is_rna[base + ig])) ? 1.0f : 0.0f;
        if (__ldg(&cmask[base + ig])) {
            itx = truec[idx + 0]; ity = truec[idx + 1]; itz = truec[idx + 2];
        }
    }

    float acc_sum = 0.f, acc_cnt = 0.f;
    const int jbase = tj * TILE;
    if (ti == tj)
        tile_loop<true >(s_p, s_t, ipx, ipy, ipz, itx, ity, itz, a_i, ig, jbase, acc_sum, acc_cnt);
    else
        tile_loop<false>(s_p, s_t, ipx, ipy, ipz, itx, ity, itz, a_i, ig, jbase, acc_sum, acc_cnt);

    // ---- block reduce ----
    #pragma unroll
    for (int o = 16; o > 0; o >>= 1) {
        acc_sum += __shfl_down_sync(0xFFFFFFFFu, acc_sum, o);
        acc_cnt += __shfl_down_sync(0xFFFFFFFFu, acc_cnt, o);
    }
    __shared__ float ws[TILE / 32];
    __shared__ float wc[TILE / 32];
    int w = tid >> 5, l = tid & 31;
    if (l == 0) { ws[w] = acc_sum; wc[w] = acc_cnt; }
    __syncthreads();

    if (tid == 0) {
        float S = 0.f, C = 0.f;
        #pragma unroll
        for (int k = 0; k < TILE / 32; k++) { S += ws[k]; C += wc[k]; }
        atomicAdd(&g_sum[b], (double)S * 0.25);   // eps = sum_of_sigmoids / 4
        atomicAdd(&g_cnt[b], (double)C);

        __threadfence();
        unsigned int done = atomicAdd(&g_done, 1u);
        if (done == total_blocks - 1u) {
            // last block: finalize, write output, reset state for next replay
            volatile double* vs = g_sum;
            volatile double* vc = g_cnt;
            double c0 = vc[0]; if (c0 < 1.0) c0 = 1.0;
            double c1 = vc[1]; if (c1 < 1.0) c1 = 1.0;
            double l0 = vs[0] / c0;
            double l1 = vs[1] / c1;
            out[0] = (float)(1.0 - 0.5 * (l0 + l1));
            g_sum[0] = 0.0; g_sum[1] = 0.0;
            g_cnt[0] = 0.0; g_cnt[1] = 0.0;
            __threadfence();
            g_done = 0u;
        }
    }
}

extern "C" void kernel_launch(void* const* d_in, const int* in_sizes, int n_in,
                              void* d_out, int out_size)
{
    const float*   pred  = (const float*)d_in[0];
    const float*   truec = (const float*)d_in[1];
    const uint8_t* dna   = (const uint8_t*)d_in[2];
    const uint8_t* rna   = (const uint8_t*)d_in[3];
    const uint8_t* cm    = (const uint8_t*)d_in[4];

    const int B = 2;
    const int n = in_sizes[2] / B;           // is_dna has b*n elements
    const int ntiles = (n + TILE - 1) / TILE;
    const int npairs = ntiles * (ntiles + 1) / 2;

    dim3 grid(npairs, B);
    lddt_fused_kernel<<<grid, TILE>>>(pred, truec, dna, rna, cm,
                                      (float*)d_out, n, ntiles,
                                      (unsigned int)(npairs * B));
}

// round 6
// speedup vs baseline: 1.3105x; 1.1975x over previous
#include <cuda_runtime.h>
#include <stdint.h>

// SmoothLDDTLoss — b=2, n=4096. Fused single kernel, f32x2-packed inner loop.
// Coords pre-scaled by sqrt(2)*LOG2E (i-side negated); distances via the
// reference's own expansion d2 = sq_i + sq_j - 2*dot, done 2-pairs-per-instr
// with fma.rn.f32x2. ex2 consumes log2-domain distance directly.

#define TILE 128
#define QN   (TILE / 2)

typedef unsigned long long ull;

__device__ double       g_sum[2];
__device__ double       g_cnt[2];
__device__ unsigned int g_done;

__device__ __forceinline__ float fsqrt_ap(float x) { float r; asm("sqrt.approx.f32 %0, %1;" : "=f"(r) : "f"(x)); return r; }
__device__ __forceinline__ float frcp_ap (float x) { float r; asm("rcp.approx.f32 %0, %1;"  : "=f"(r) : "f"(x)); return r; }
__device__ __forceinline__ float fex2_ap (float x) { float r; asm("ex2.approx.f32 %0, %1;"  : "=f"(r) : "f"(x)); return r; }

__device__ __forceinline__ ull pk2(float lo, float hi) { ull r; asm("mov.b64 %0, {%1, %2};" : "=l"(r) : "f"(lo), "f"(hi)); return r; }
__device__ __forceinline__ void upk2(float& lo, float& hi, ull v) { asm("mov.b64 {%0, %1}, %2;" : "=f"(lo), "=f"(hi) : "l"(v)); }
__device__ __forceinline__ ull fma2(ull a, ull b, ull c) { ull d; asm("fma.rn.f32x2 %0, %1, %2, %3;" : "=l"(d) : "l"(a), "l"(b), "l"(c)); return d; }
__device__ __forceinline__ ull mul2(ull a, ull b) { ull d; asm("mul.rn.f32x2 %0, %1, %2;" : "=l"(d) : "l"(a), "l"(b)); return d; }
__device__ __forceinline__ ull add2(ull a, ull b) { ull d; asm("add.rn.f32x2 %0, %1, %2;" : "=l"(d) : "l"(a), "l"(b)); return d; }

#define LOG2E  1.44269504088896340f
#define SC     2.04022209793536f     /* sqrt(2)*LOG2E */
#define L2     2.08136899f           /* LOG2E^2 */
#define CLAMP  14.4269504088896f     /* 10 * LOG2E: keeps den finite, kills inf/NaN */
// sigmoid constants e^{-0.5}, e^{-1}, e^{-2}, e^{-4}
#define C1 0.60653065971263342f
#define C2 0.36787944117144233f
#define C3 0.13533528323661270f
#define C4 0.01831563888873418f

// smem word layout per q (pair of j points), 10 u64 = 20 floats:
// 0:pxp 1:pyp 2:pzp 3:txp 4:typ 5:tzp 6:sqpp 7:sqtp 8:r2p 9:pad
struct SmemQ { ulonglong2 v[5]; };

template<bool DIAG>
__device__ __forceinline__ void tile_loop(
    const SmemQ* __restrict__ W,
    ull nix2, ull niy2, ull niz2, ull ntx2, ull nty2, ull ntz2,
    ull sqip2, ull sqit2, float ri2, int ig, int jbase,
    ull& accs, ull& accc,
    ull K1, ull K2, ull K3, ull K4, ull ONE2)
{
    #pragma unroll 2
    for (int q = 0; q < QN; q++) {
        ulonglong2 g0 = W[q].v[0];   // pxp, pyp
        ulonglong2 g1 = W[q].v[1];   // pzp, txp
        ulonglong2 g2 = W[q].v[2];   // typ, tzp
        ulonglong2 g3 = W[q].v[3];   // sqpp, sqtp
        ull r2p       = W[q].v[4].x; // r2 pair

        ull dp2p = fma2(nix2, g0.x, fma2(niy2, g0.y, fma2(niz2, g1.x, add2(sqip2, g3.x))));
        ull dt2p = fma2(ntx2, g1.y, fma2(nty2, g2.x, fma2(ntz2, g2.y, add2(sqit2, g3.y))));

        float dp0, dp1, dt0, dt1;
        upk2(dp0, dp1, dp2p);
        upk2(dt0, dt1, dt2p);
        dp0 = fmaxf(dp0, 0.0f); dp1 = fmaxf(dp1, 0.0f);
        dt0 = fmaxf(dt0, 0.0f); dt1 = fmaxf(dt1, 0.0f);

        float sp0 = fsqrt_ap(dp0), sp1 = fsqrt_ap(dp1);
        float st0 = fsqrt_ap(dt0), st1 = fsqrt_ap(dt1);

        float f0 = fminf(fabsf(st0 - sp0), CLAMP);
        float f1 = fminf(fabsf(st1 - sp1), CLAMP);
        float e0 = fex2_ap(f0);
        float e1 = fex2_ap(f1);
        ull e2 = pk2(e0, e1);

        ull u1 = fma2(e2, K1, ONE2);
        ull u2 = fma2(e2, K2, ONE2);
        ull u3 = fma2(e2, K3, ONE2);
        ull u4 = fma2(e2, K4, ONE2);
        ull A2 = mul2(u1, u2), B2 = mul2(u3, u4);
        ull s12 = add2(u1, u2), s34 = add2(u3, u4);
        ull num2 = fma2(s12, B2, mul2(s34, A2));
        ull den2 = mul2(A2, B2);

        float d0, d1;
        upk2(d0, d1, den2);
        float r = frcp_ap(d0 * d1);              // one rcp for both pairs
        ull t2 = pk2(r * d1, r * d0);
        ull eps2 = mul2(num2, t2);               // (sum of 4 sigmoids) per pair

        float r20, r21;
        upk2(r20, r21, r2p);
        float R20 = fminf(ri2, r20);             // both-nuc => 900L2 else 225L2 (0 => never)
        float R21 = fminf(ri2, r21);
        bool v0 = dt0 < R20;
        bool v1 = dt1 < R21;
        if (DIAG) {
            v0 = v0 && (jbase + 2 * q     > ig);
            v1 = v1 && (jbase + 2 * q + 1 > ig);
        }
        float m0 = v0 ? 1.0f : 0.0f;
        float m1 = v1 ? 1.0f : 0.0f;
        ull m2 = pk2(m0, m1);

        accs = fma2(eps2, m2, accs);             // NaN-free by construction (clamp)
        accc = add2(accc, m2);
    }
}

__global__ void __launch_bounds__(TILE) lddt_fused_kernel(
    const float* __restrict__ pred,
    const float* __restrict__ truec,
    const uint8_t* __restrict__ is_dna,
    const uint8_t* __restrict__ is_rna,
    const uint8_t* __restrict__ cmask,
    float* __restrict__ out,
    int n, int ntiles, unsigned int total_blocks)
{
    // closed-form triangular decode: blockIdx.x -> (ti, tj), ti <= tj
    int t = blockIdx.x;
    float Nf = (float)ntiles;
    float disc = fmaf(2.0f, Nf, 1.0f);
    float s    = sqrtf(fmaf(disc, disc, -8.0f * (float)t));
    int ti = (int)floorf(0.5f * (disc - s));
    if (ti < 0) ti = 0;
    if (ti > ntiles - 1) ti = ntiles - 1;
    #pragma unroll
    for (int k = 0; k < 2; k++) {
        int row_off  = ti * ntiles - (ti * (ti - 1)) / 2;
        int next_off = (ti + 1) * ntiles - ((ti + 1) * ti) / 2;
        if (t < row_off)        ti--;
        else if (t >= next_off) ti++;
    }
    int row_off = ti * ntiles - (ti * (ti - 1)) / 2;
    int tj = ti + (t - row_off);
    if (tj < ti) tj = ti;
    if (tj > ntiles - 1) tj = ntiles - 1;

    const int b = blockIdx.y;
    const int tid = threadIdx.x;
    const long base = (long)b * n;

    __shared__ SmemQ W[QN];

    // ---- fill j tile (scaled coords, norms, radii) ----
    {
        int jg = tj * TILE + tid;
        float px = 0.f, py = 0.f, pz = 0.f, tx = 0.f, ty = 0.f, tz = 0.f;
        float sqp = 0.f, sqt = 0.f, r2 = 0.f;
        if (jg < n) {
            long idx = (base + jg) * 3;
            px = pred[idx + 0] * SC; py = pred[idx + 1] * SC; pz = pred[idx + 2] * SC;
            tx = truec[idx + 0] * SC; ty = truec[idx + 1] * SC; tz = truec[idx + 2] * SC;
            sqp = 0.5f * fmaf(px, px, fmaf(py, py, pz * pz));     // = L2*|p|^2
            sqt = 0.5f * fmaf(tx, tx, fmaf(ty, ty, tz * tz));
            bool nuc = (__ldg(&is_dna[base + jg]) | __ldg(&is_rna[base + jg])) != 0;
            r2 = nuc ? 900.0f * L2 : 225.0f * L2;
            if (!__ldg(&cmask[base + jg])) sqt += 1e30f;          // poison: dt2 huge
        }
        float* F = (float*)W;
        int q = tid >> 1, l = tid & 1;
        int o = q * 20 + l;
        F[o +  0] = px;  F[o +  2] = py;  F[o +  4] = pz;
        F[o +  6] = tx;  F[o +  8] = ty;  F[o + 10] = tz;
        F[o + 12] = sqp; F[o + 14] = sqt; F[o + 16] = r2;
    }
    __syncthreads();

    // ---- own i point (negated scaled coords for the fma-dot chain) ----
    const int ig = ti * TILE + tid;
    float nix = 0.f, niy = 0.f, niz = 0.f, ntx = 0.f, nty = 0.f, ntz = 0.f;
    float sqip = 0.f, sqit = 0.f, ri2 = 0.f;
    if (ig < n) {
        long idx = (base + ig) * 3;
        float ax = pred[idx + 0] * SC, ay = pred[idx + 1] * SC, az = pred[idx + 2] * SC;
        float bx = truec[idx + 0] * SC, by = truec[idx + 1] * SC, bz = truec[idx + 2] * SC;
        sqip = 0.5f * fmaf(ax, ax, fmaf(ay, ay, az * az));
        sqit = 0.5f * fmaf(bx, bx, fmaf(by, by, bz * bz));
        nix = -ax; niy = -ay; niz = -az;
        ntx = -bx; nty = -by; ntz = -bz;
        bool nuc = (__ldg(&is_dna[base + ig]) | __ldg(&is_rna[base + ig])) != 0;
        ri2 = nuc ? 900.0f * L2 : 225.0f * L2;
        if (!__ldg(&cmask[base + ig])) sqit += 1e30f;
    }

    ull nix2 = pk2(nix, nix), niy2 = pk2(niy, niy), niz2 = pk2(niz, niz);
    ull ntx2 = pk2(ntx, ntx), nty2 = pk2(nty, nty), ntz2 = pk2(ntz, ntz);
    ull sqip2 = pk2(sqip, sqip), sqit2 = pk2(sqit, sqit);
    ull K1 = pk2(C1, C1), K2 = pk2(C2, C2), K3 = pk2(C3, C3), K4 = pk2(C4, C4);
    ull ONE2 = pk2(1.0f, 1.0f);

    ull accs = 0ull, accc = 0ull;   // packed (0.0f, 0.0f)
    const int jbase = tj * TILE;
    if (ti == tj)
        tile_loop<true >(W, nix2, niy2, niz2, ntx2, nty2, ntz2, sqip2, sqit2, ri2, ig, jbase, accs, accc, K1, K2, K3, K4, ONE2);
    else
        tile_loop<false>(W, nix2, niy2, niz2, ntx2, nty2, ntz2, sqip2, sqit2, ri2, ig, jbase, accs, accc, K1, K2, K3, K4, ONE2);

    float a0, a1, c0, c1;
    upk2(a0, a1, accs);
    upk2(c0, c1, accc);
    float acc_sum = a0 + a1;
    float acc_cnt = c0 + c1;

    // ---- block reduce ----
    #pragma unroll
    for (int o = 16; o > 0; o >>= 1) {
        acc_sum += __shfl_down_sync(0xFFFFFFFFu, acc_sum, o);
        acc_cnt += __shfl_down_sync(0xFFFFFFFFu, acc_cnt, o);
    }
    __shared__ float ws[TILE / 32];
    __shared__ float wc[TILE / 32];
    int w = tid >> 5, l = tid & 31;
    if (l == 0) { ws[w] = acc_sum; wc[w] = acc_cnt; }
    __syncthreads();

    if (tid == 0) {
        float S = 0.f, C = 0.f;
        #pragma unroll
        for (int k = 0; k < TILE / 32; k++) { S += ws[k]; C += wc[k]; }
        atomicAdd(&g_sum[b], (double)S * 0.25);
        atomicAdd(&g_cnt[b], (double)C);

        __threadfence();
        unsigned int done = atomicAdd(&g_done, 1u);
        if (done == total_blocks - 1u) {
            volatile double* vs = g_sum;
            volatile double* vc = g_cnt;
            double cc0 = vc[0]; if (cc0 < 1.0) cc0 = 1.0;
            double cc1 = vc[1]; if (cc1 < 1.0) cc1 = 1.0;
            double l0 = vs[0] / cc0;
            double l1 = vs[1] / cc1;
            out[0] = (float)(1.0 - 0.5 * (l0 + l1));
            g_sum[0] = 0.0; g_sum[1] = 0.0;
            g_cnt[0] = 0.0; g_cnt[1] = 0.0;
            __threadfence();
            g_done = 0u;
        }
    }
}

extern "C" void kernel_launch(void* const* d_in, const int* in_sizes, int n_in,
                              void* d_out, int out_size)
{
    const float*   pred  = (const float*)d_in[0];
    const float*   truec = (const float*)d_in[1];
    const uint8_t* dna   = (const uint8_t*)d_in[2];
    const uint8_t* rna   = (const uint8_t*)d_in[3];
    const uint8_t* cm    = (const uint8_t*)d_in[4];

    const int B = 2;
    const int n = in_sizes[2] / B;
    const int ntiles = (n + TILE - 1) / TILE;
    const int npairs = ntiles * (ntiles + 1) / 2;

    dim3 grid(npairs, B);
    lddt_fused_kernel<<<grid, TILE>>>(pred, truec, dna, rna, cm,
                                      (float*)d_out, n, ntiles,
                                      (unsigned int)(npairs * B));
}